// round 3
// baseline (speedup 1.0000x reference)
#include <cuda_runtime.h>
#include <cstdint>

#define BB 512
#define TT 4096
#define SS 64
#define MM 125

// obs scratch (+4 pad so the obs-word lookahead never reads OOB)
__device__ __align__(16) unsigned char g_obs[BB * TT + 4];

// ---------------------------------------------------------------------------
// Kernel 1: decode one-hot rows -> obs indices.
// Pure streaming float4 read of the whole tensor at HBM rate; hits are rare
// (1 per 31.25 float4s) and write a single scattered byte.
// ---------------------------------------------------------------------------
__global__ void __launch_bounds__(256) decode_kernel(const float4* __restrict__ x4) {
    const unsigned n4 = (unsigned)((long long)BB * TT * MM / 4);   // 65,536,000
    const unsigned stride = gridDim.x * 256u;
    for (unsigned i = blockIdx.x * 256u + threadIdx.x; i < n4; i += stride) {
        float4 v = __ldcs(x4 + i);
        // a float4 can straddle a row boundary -> check all 4 components
        if (v.x > 0.5f) { unsigned j = 4u * i + 0u; unsigned r = j / 125u; g_obs[r] = (unsigned char)(j - r * 125u); }
        if (v.y > 0.5f) { unsigned j = 4u * i + 1u; unsigned r = j / 125u; g_obs[r] = (unsigned char)(j - r * 125u); }
        if (v.z > 0.5f) { unsigned j = 4u * i + 2u; unsigned r = j / 125u; g_obs[r] = (unsigned char)(j - r * 125u); }
        if (v.w > 0.5f) { unsigned j = 4u * i + 3u; unsigned r = j / 125u; g_obs[r] = (unsigned char)(j - r * 125u); }
    }
}

// packed f32x2 FMA — only reachable via PTX (ptxas never auto-fuses)
__device__ __forceinline__ void ffma2(float2& d, float2 a, float2 b, float2 c) {
    asm("fma.rn.f32x2 %0, %1, %2, %3;"
        : "=l"(*(unsigned long long*)&d)
        : "l"(*(unsigned long long*)&a),
          "l"(*(unsigned long long*)&b),
          "l"(*(unsigned long long*)&c));
}

// ---------------------------------------------------------------------------
// Kernel 2: HMM forward scan. One warp per batch chain.
// lane j owns states {j, j+32}; A column k-pairs live in 128 registers.
// alpha ping-pongs through shared. Rescaling every 8 steps uses an exact
// power-of-two scale derived from lane 0's exponent (no reduction, no log);
// the single exact log + full sum happens once at the end.
// ---------------------------------------------------------------------------
__global__ void __launch_bounds__(128) scan_kernel(
    const float* __restrict__ Ivec,
    const float* __restrict__ A,
    const float* __restrict__ Bm,
    float* __restrict__ out)
{
    __shared__ float2 sB2[MM * 32];                // e-pair table: (Bm[m][l], Bm[m][l+32])
    __shared__ float sAlpha[4][2][SS];             // per-warp double buffer

    const int tid = threadIdx.x;
    const int w = tid >> 5;
    const int lane = tid & 31;
    const int b = blockIdx.x * 4 + w;

    // stage Bm into shared as float2 pairs so E lookup is a single LDS.64
    for (int i = tid; i < MM * 32; i += 128) {
        int m = i >> 5, l = i & 31;
        sB2[i] = make_float2(Bm[m * SS + l], Bm[m * SS + 32 + l]);
    }
    __syncthreads();

    // A column k-pairs in registers (loop-invariant)
    float2 aA[32], aB[32];
#pragma unroll
    for (int kp = 0; kp < 32; kp++) {
        aA[kp].x = A[(2 * kp)     * SS + lane];
        aA[kp].y = A[(2 * kp + 1) * SS + lane];
        aB[kp].x = A[(2 * kp)     * SS + lane + 32];
        aB[kp].y = A[(2 * kp + 1) * SS + lane + 32];
    }

    const float i0 = Ivec[lane];
    const float i1 = Ivec[lane + 32];

    // obs words: warp-uniform LDG with one-word lookahead (L1-resident)
    const unsigned* gob32 = (const unsigned*)(g_obs + b * TT);
    unsigned obsw = __ldg(gob32);
    unsigned obsn = __ldg(gob32 + 1);

    // t = 0: u = E0 * I  (unnormalized; log-scale tracked via esum)
    int ob = obsw & 0xff;
    float2 e = sB2[ob * 32 + lane];
    float u0 = e.x * i0;
    float u1 = e.y * i1;
    sAlpha[w][0][lane]      = u0;
    sAlpha[w][0][lane + 32] = u1;
    int esum = 0;
    __syncwarp();

    for (int t = 1; t < TT; t++) {
        if ((t & 3) == 0) {
            obsw = obsn;
            obsn = __ldg(gob32 + (t >> 2) + 1);    // pad covers last batch
        }
        ob = (obsw >> ((t & 3) * 8)) & 0xff;
        e = sB2[ob * 32 + lane];                   // issued before the FMA chain

        const int rb = (t - 1) & 1;
        const int wb = t & 1;

        // R[s] = sum_k alpha[k] * A[k][s]   (64 FFMA2, 4 independent chains)
        const float4* ap = (const float4*)sAlpha[w][rb];
        float2 accA0 = {0.f, 0.f}, accA1 = {0.f, 0.f};
        float2 accB0 = {0.f, 0.f}, accB1 = {0.f, 0.f};
#pragma unroll
        for (int q = 0; q < 16; q++) {
            float4 al = ap[q];
            float2 alo = make_float2(al.x, al.y);
            float2 ahi = make_float2(al.z, al.w);
            ffma2(accA0, alo, aA[2 * q],     accA0);
            ffma2(accA1, ahi, aA[2 * q + 1], accA1);
            ffma2(accB0, alo, aB[2 * q],     accB0);
            ffma2(accB1, ahi, aB[2 * q + 1], accB1);
        }
        float r0 = (accA0.x + accA0.y) + (accA1.x + accA1.y);
        float r1 = (accB0.x + accB0.y) + (accB1.x + accB1.y);
        u0 = e.x * r0;
        u1 = e.y * r1;

        // every 8 steps: exact power-of-two rescale from lane 0's exponent
        if ((t & 7) == 7) {
            float w0 = __shfl_sync(0xffffffffu, u0, 0);
            int ex = (int)((__float_as_uint(w0) >> 23) & 0xff) - 127;
            esum += ex;
            float sc = __uint_as_float((unsigned)(127 - ex) << 23);   // 2^-ex
            u0 *= sc;
            u1 *= sc;
        }

        sAlpha[w][wb][lane]      = u0;
        sAlpha[w][wb][lane + 32] = u1;
        __syncwarp();
    }

    // single exact reduction + log at the end:
    // ll = log(sum_s alpha_hat) = esum*ln2 + log(sum_s v)
    float s = u0 + u1;
#pragma unroll
    for (int o = 16; o; o >>= 1) s += __shfl_xor_sync(0xffffffffu, s, o);
    if (lane == 0) out[b] = (float)esum * 0.6931471805599453f + logf(s);
}

extern "C" void kernel_launch(void* const* d_in, const int* in_sizes, int n_in,
                              void* d_out, int out_size) {
    const float* x  = (const float*)d_in[0];   // [512, 4096, 125]
    const float* I  = (const float*)d_in[1];   // [1, 64]
    const float* A  = (const float*)d_in[2];   // [64, 64]
    const float* Bm = (const float*)d_in[3];   // [125, 64]
    float* out = (float*)d_out;                // [512, 1]

    decode_kernel<<<64000, 256>>>((const float4*)x);
    scan_kernel<<<BB / 4, 128>>>(I, A, Bm, out);
}

// round 6
// speedup vs baseline: 1.2848x; 1.2848x over previous
#include <cuda_runtime.h>
#include <cstdint>

#define BB 512
#define TT 4096
#define SS 64
#define MM 125
#define CHUNK 512                 // time-steps per producer/consumer chunk
#define NCHUNK (TT / CHUNK)       // 8

// packed f32x2 FMA — only reachable via PTX (ptxas never auto-fuses)
__device__ __forceinline__ void ffma2(float2& d, float2 a, float2 b, float2 c) {
    asm("fma.rn.f32x2 %0, %1, %2, %3;"
        : "=l"(*(unsigned long long*)&d)
        : "l"(*(unsigned long long*)&a),
          "l"(*(unsigned long long*)&b),
          "l"(*(unsigned long long*)&c));
}

// pair rendezvous: scanner warp p and decoder warp p+4, named barrier p+1
__device__ __forceinline__ void pair_bar(int p) {
    asm volatile("bar.sync %0, 64;" :: "r"(p + 1) : "memory");
}

// One HMM forward step for one warp-owned chain.
// lane owns states {lane, lane+32}. cur/nxt are 64-float smem alpha buffers.
__device__ __forceinline__ void hmm_step(
    int ob, const float2* __restrict__ sB2,
    const float* cur, float* nxt,
    const float2* aA, const float2* aB,
    float& u0, float& u1, int& esum, int t, int lane)
{
    float2 e = sB2[ob * 32 + lane];               // LDS.64, independent of alpha
    const float4* ap = (const float4*)cur;
    float2 accA0 = {0.f, 0.f}, accA1 = {0.f, 0.f};
    float2 accB0 = {0.f, 0.f}, accB1 = {0.f, 0.f};
#pragma unroll
    for (int q = 0; q < 16; q++) {
        float4 al = ap[q];                        // alpha[4q..4q+3] broadcast
        float2 alo = make_float2(al.x, al.y);
        float2 ahi = make_float2(al.z, al.w);
        ffma2(accA0, alo, aA[2 * q],     accA0);
        ffma2(accA1, ahi, aA[2 * q + 1], accA1);
        ffma2(accB0, alo, aB[2 * q],     accB0);
        ffma2(accB1, ahi, aB[2 * q + 1], accB1);
    }
    float r0 = (accA0.x + accA0.y) + (accA1.x + accA1.y);
    float r1 = (accB0.x + accB0.y) + (accB1.x + accB1.y);
    u0 = e.x * r0;
    u1 = e.y * r1;

    // every 8 steps: exact power-of-two rescale from lane 0's exponent
    // (log of the scale accumulates in esum; exact log once at the end)
    if ((t & 7) == 7) {
        float w0 = __shfl_sync(0xffffffffu, u0, 0);
        int ex = (int)((__float_as_uint(w0) >> 23) & 0xff) - 127;
        esum += ex;
        float sc = __uint_as_float((unsigned)(127 - ex) << 23);   // 2^-ex
        u0 *= sc;
        u1 *= sc;
    }

    nxt[lane]      = u0;
    nxt[lane + 32] = u1;
    // warp is convergent: same-warp STS->LDS is HW-ordered; block only the
    // compiler from reordering smem accesses across iterations.
    asm volatile("" ::: "memory");
}

// ---------------------------------------------------------------------------
// Fused kernel: 4 scanner warps (one chain each) + 4 decoder warps per CTA.
// Decoder warp p+4 streams chain p's one-hot rows and argmax-decodes them into
// a double-buffered smem byte array, one 512-step chunk ahead of its scanner.
// ---------------------------------------------------------------------------
__global__ void __launch_bounds__(256) fused_hmm_kernel(
    const float* __restrict__ x,
    const float* __restrict__ Ivec,
    const float* __restrict__ A,
    const float* __restrict__ Bm,
    float* __restrict__ out)
{
    __shared__ float2 sB2[MM * 32];                         // 32000 B
    __shared__ float sAlpha[4][2][SS];                      //  2048 B
    __shared__ unsigned char sObs[4][2][CHUNK];             //  4096 B

    const int tid  = threadIdx.x;
    const int w    = tid >> 5;          // 0..7
    const int lane = tid & 31;
    const int p    = w & 3;             // pair id / chain slot in CTA
    const int b    = blockIdx.x * 4 + p;

    // stage Bm into shared as (Bm[m][l], Bm[m][l+32]) pairs — all 256 threads
    for (int i = tid; i < MM * 32; i += 256) {
        int m = i >> 5, l = i & 31;
        sB2[i] = make_float2(Bm[m * SS + l], Bm[m * SS + 32 + l]);
    }
    __syncthreads();

    if (w >= 4) {
        // ------------------ decoder warp for chain b ------------------
        const float4* xc = (const float4*)(x + (size_t)b * TT * MM);
        for (int c = 0; c < NCHUNK; c++) {
            unsigned char* dst = sObs[p][c & 1];
            const float4* base = xc + c * (CHUNK * MM / 4);   // 16000 float4/chunk
            const unsigned jbase = c * (CHUNK * MM);
            const unsigned rbase = c * CHUNK;
            for (int i = lane; i < CHUNK * MM / 4; i += 32) {
                float4 v = __ldcs(base + i);
                unsigned j = jbase + 4u * i;
                if (v.x > 0.5f) { unsigned r = j / 125u;        dst[r - rbase] = (unsigned char)(j - r * 125u); }
                if (v.y > 0.5f) { unsigned r = (j + 1) / 125u;  dst[r - rbase] = (unsigned char)(j + 1 - r * 125u); }
                if (v.z > 0.5f) { unsigned r = (j + 2) / 125u;  dst[r - rbase] = (unsigned char)(j + 2 - r * 125u); }
                if (v.w > 0.5f) { unsigned r = (j + 3) / 125u;  dst[r - rbase] = (unsigned char)(j + 3 - r * 125u); }
            }
            pair_bar(p);   // chunk c ready; scanner freed buffer (c-2) by arriving
        }
    } else {
        // ------------------ scanner warp for chain b ------------------
        // A column k-pairs in registers (loop-invariant):
        float2 aA[32], aB[32];
#pragma unroll
        for (int kp = 0; kp < 32; kp++) {
            aA[kp].x = A[(2 * kp)     * SS + lane];
            aA[kp].y = A[(2 * kp + 1) * SS + lane];
            aB[kp].x = A[(2 * kp)     * SS + lane + 32];
            aB[kp].y = A[(2 * kp + 1) * SS + lane + 32];
        }
        const float i0 = Ivec[lane];
        const float i1 = Ivec[lane + 32];

        float* buf0 = sAlpha[p][0];
        float* buf1 = sAlpha[p][1];
        float u0, u1;
        int esum = 0;

        // ---- chunk 0 ----
        pair_bar(p);
        {
            int ob = sObs[p][0][0];
            float2 e = sB2[ob * 32 + lane];
            u0 = e.x * i0;                        // t=0: u = E0 * I (unnormalized)
            u1 = e.y * i1;
            buf0[lane]      = u0;
            buf0[lane + 32] = u1;
            asm volatile("" ::: "memory");
        }
        float* cur = buf0;
        float* nxt = buf1;
        {
            const unsigned char* obp = sObs[p][0];
            for (int tt = 1; tt < CHUNK; tt++) {
                hmm_step(obp[tt], sB2, cur, nxt, aA, aB, u0, u1, esum, tt, lane);
                float* tmp = cur; cur = nxt; nxt = tmp;
            }
        }
        // ---- chunks 1..7 ----
        for (int c = 1; c < NCHUNK; c++) {
            pair_bar(p);
            const unsigned char* obp = sObs[p][c & 1];
            const int tb = c * CHUNK;
            for (int tt = 0; tt < CHUNK; tt++) {
                hmm_step(obp[tt], sB2, cur, nxt, aA, aB, u0, u1, esum, tb + tt, lane);
                float* tmp = cur; cur = nxt; nxt = tmp;
            }
        }

        // single exact reduction + log at the end:
        float s = u0 + u1;
#pragma unroll
        for (int o = 16; o; o >>= 1) s += __shfl_xor_sync(0xffffffffu, s, o);
        if (lane == 0) out[b] = (float)esum * 0.6931471805599453f + logf(s);
    }
}

extern "C" void kernel_launch(void* const* d_in, const int* in_sizes, int n_in,
                              void* d_out, int out_size) {
    const float* x  = (const float*)d_in[0];   // [512, 4096, 125]
    const float* I  = (const float*)d_in[1];   // [1, 64]
    const float* A  = (const float*)d_in[2];   // [64, 64]
    const float* Bm = (const float*)d_in[3];   // [125, 64]
    float* out = (float*)d_out;                // [512, 1]

    fused_hmm_kernel<<<BB / 4, 256>>>(x, I, A, Bm, out);
}